// round 14
// baseline (speedup 1.0000x reference)
#include <cuda_runtime.h>
#include <math.h>

// ---------------- problem constants ----------------
#define NTOT   12288         // H*W*3
#define BATCH  64
#define KCH    4096          // K per k-split slice
#define NKC    3
#define NTILE  128           // output cols per CTA
#define KSTAGE 32            // k per smem stage
#define NSTAGE (KCH / KSTAGE)   // 128

// k-split partials: [NKC][BATCH][NTOT]  (~9.4 MB scratch)
__device__ __align__(16) float g_part[NKC * BATCH * NTOT];

// ---------------- smem layout (bytes) ----------------
// AH plane: [2 buf][64 m][80 B]  (32 fp16 + pad)   per buf-plane 5120
// BH plane: [2 buf][32 k][272 B] (128 fp16 + pad)  per buf-plane 8704
#define A_STRIDE 80
#define B_STRIDE 272
#define OFF_AH  0
#define OFF_BH  10240
#define SMEMA_TOTAL 27648

__device__ __forceinline__ unsigned smem_u32(const void* p) {
    unsigned a;
    asm("{ .reg .u64 t; cvta.to.shared.u64 t, %1; cvt.u32.u64 %0, t; }" : "=r"(a) : "l"(p));
    return a;
}

// pack two f32 -> f16x2 (lo = a, hi = b)
__device__ __forceinline__ unsigned packf16(float a, float b) {
    unsigned r;
    asm("cvt.rn.f16x2.f32 %0, %1, %2;" : "=r"(r) : "f"(b), "f"(a));
    return r;
}

#define LDMX4(r0, r1, r2, r3, addr) \
    asm volatile("ldmatrix.sync.aligned.m8n8.x4.shared.b16 {%0,%1,%2,%3}, [%4];" \
                 : "=r"(r0), "=r"(r1), "=r"(r2), "=r"(r3) : "r"(addr))
#define LDMX4T(r0, r1, r2, r3, addr) \
    asm volatile("ldmatrix.sync.aligned.m8n8.x4.trans.shared.b16 {%0,%1,%2,%3}, [%4];" \
                 : "=r"(r0), "=r"(r1), "=r"(r2), "=r"(r3) : "r"(addr))
#define MMA16816(d, a, b) \
    asm volatile("mma.sync.aligned.m16n8k16.row.col.f32.f16.f16.f32 " \
                 "{%0,%1,%2,%3}, {%4,%5,%6,%7}, {%8,%9}, {%0,%1,%2,%3};" \
                 : "+f"((d)[0]), "+f"((d)[1]), "+f"((d)[2]), "+f"((d)[3]) \
                 : "r"((a)[0]), "r"((a)[1]), "r"((a)[2]), "r"((a)[3]), \
                   "r"((b)[0]), "r"((b)[1]))

// B-tile global load for one stage (4x float4 per thread)
#define LOAD_B(dst, stage) do {                                                  \
    const int _ks = k0 + (stage) * KSTAGE;                                       \
    _Pragma("unroll")                                                            \
    for (int _p = 0; _p < 4; ++_p) {                                             \
        const float* _bp = W + (size_t)(_ks + wid + 8 * _p) * NTOT + n0 + 4 * lane; \
        (dst)[_p] = *(const float4*)_bp;                                         \
    }                                                                            \
} while (0)

// B-tile convert + STS (consumes 4x float4)
#define STS_B(src, bufp) do {                                                    \
    char* _BH = smem + OFF_BH + (bufp) * 8704;                                   \
    _Pragma("unroll")                                                            \
    for (int _p = 0; _p < 4; ++_p) {                                             \
        unsigned _h0 = packf16((src)[_p].x, (src)[_p].y);                        \
        unsigned _h1 = packf16((src)[_p].z, (src)[_p].w);                        \
        const unsigned _bo = (unsigned)((wid + 8 * _p) * B_STRIDE + 8 * lane);   \
        *(uint2*)(_BH + _bo) = make_uint2(_h0, _h1);                             \
    }                                                                            \
} while (0)

// ================= Kernel A: mma.sync fp16 single-pass GEMM =================
// C[64, 128] partial over k-chunk 4096. 8 warps = 2M x 4N, warp 32x32.
// A = fp16(obs), B = fp16(W). Distance-2 register pipeline on the W stream:
// LDG(s+2) issued at stage s -> 2-stage in-flight window covers DRAM latency.
__global__ __launch_bounds__(256, 2)
void gemm_mma(const float* __restrict__ obs, const float* __restrict__ W)
{
    extern __shared__ char smem[];
    const unsigned sbase = smem_u32(smem);
    const int tid  = threadIdx.x;
    const int lane = tid & 31;
    const int wid  = tid >> 5;
    const int n0   = blockIdx.x * NTILE;
    const int k0   = blockIdx.y * KCH;

    const int wm = wid >> 2;
    const int wn = wid & 3;
    const int mbase = 32 * wm;
    const int nbase = 32 * wn;

    // loader mappings
    const int am = tid >> 2;          // A row m 0..63
    const int aq = tid & 3;           // A k-octet

    // ldmatrix lane address components
    const int a_mo = ((lane >> 3) & 1) * 8 + (lane & 7);
    const int a_ko = (lane >> 4) * 8;
    const int b_k  = lane & 15;
    const int b_no = (lane >> 4) * 8;

    float4 a4[2];
    float4 b0[4], b1[4];    // distance-2 rotating B buffers

    // prologue: A(0), B(0), B(1)
    {
        const float* ap = obs + (size_t)am * NTOT + k0 + 8 * aq;
        a4[0] = *(const float4*)ap;
        a4[1] = *(const float4*)(ap + 4);
    }
    LOAD_B(b0, 0);
    LOAD_B(b1, 1);

    float acc[2][4][4];
    #pragma unroll
    for (int mf = 0; mf < 2; ++mf)
        #pragma unroll
        for (int nf = 0; nf < 4; ++nf)
            #pragma unroll
            for (int q = 0; q < 4; ++q) acc[mf][nf][q] = 0.f;

    for (int s = 0; s < NSTAGE; ++s) {
        const int buf = s & 1;

        // ---- A: convert + STS stage s ----
        {
            char* AH = smem + OFF_AH + buf * 5120;
            unsigned h0 = packf16(a4[0].x, a4[0].y);
            unsigned h1 = packf16(a4[0].z, a4[0].w);
            unsigned h2 = packf16(a4[1].x, a4[1].y);
            unsigned h3 = packf16(a4[1].z, a4[1].w);
            *(uint4*)(AH + (unsigned)(am * A_STRIDE + 16 * aq)) = make_uint4(h0, h1, h2, h3);
        }
        // ---- B: STS stage s (loaded at s-2), then LDG stage s+2 ----
        if (buf == 0) {
            STS_B(b0, 0);
            if (s + 2 < NSTAGE) LOAD_B(b0, s + 2);
        } else {
            STS_B(b1, 1);
            if (s + 2 < NSTAGE) LOAD_B(b1, s + 2);
        }
        // ---- A: LDG stage s+1 (L2-resident; distance-1 suffices) ----
        if (s + 1 < NSTAGE) {
            const float* ap = obs + (size_t)am * NTOT + k0 + (s + 1) * KSTAGE + 8 * aq;
            a4[0] = *(const float4*)ap;
            a4[1] = *(const float4*)(ap + 4);
        }

        __syncthreads();   // single barrier per stage (ping-pong WAR-safe)

        // ---- compute stage s: 2 k16 steps, single pass ----
        const unsigned AHb = sbase + OFF_AH + buf * 5120;
        const unsigned BHb = sbase + OFF_BH + buf * 8704;

        #pragma unroll
        for (int kb = 0; kb < 2; ++kb) {
            unsigned ah[2][4];
            #pragma unroll
            for (int mf = 0; mf < 2; ++mf) {
                const unsigned aoff =
                    (unsigned)((mbase + 16 * mf + a_mo) * A_STRIDE + (kb * 16 + a_ko) * 2);
                LDMX4(ah[mf][0], ah[mf][1], ah[mf][2], ah[mf][3], AHb + aoff);
            }
            unsigned bh[4][2];
            #pragma unroll
            for (int g = 0; g < 2; ++g) {
                const unsigned boff =
                    (unsigned)((kb * 16 + b_k) * B_STRIDE + (nbase + 16 * g + b_no) * 2);
                LDMX4T(bh[2*g][0], bh[2*g][1], bh[2*g+1][0], bh[2*g+1][1], BHb + boff);
            }
            #pragma unroll
            for (int mf = 0; mf < 2; ++mf)
                #pragma unroll
                for (int nf = 0; nf < 4; ++nf)
                    MMA16816(acc[mf][nf], ah[mf], bh[nf]);
        }
    }

    // ---- epilogue ----
    float* op = g_part + (size_t)blockIdx.y * (BATCH * NTOT);
    const int r0 = lane >> 2;
    const int c0 = 2 * (lane & 3);
    #pragma unroll
    for (int mf = 0; mf < 2; ++mf)
        #pragma unroll
        for (int nf = 0; nf < 4; ++nf) {
            const int m = mbase + 16 * mf + r0;
            const int n = n0 + nbase + 8 * nf + c0;
            *(float2*)(op + (size_t)m * NTOT + n) =
                make_float2(acc[mf][nf][0], acc[mf][nf][1]);
            *(float2*)(op + (size_t)(m + 8) * NTOT + n) =
                make_float2(acc[mf][nf][2], acc[mf][nf][3]);
        }
}

// ================= Kernel B: combine + softmax + VIN + head =================
// 1024 threads, no sC staging (constants straight to registers).
// V padded grid: 66 rows x stride 68, left-pad 4: V(h,w) at (h+1)*68 + 4 + w.
#define NTB  1024
#define VROW 68
#define VSZ  (66 * VROW)     // 4488
#define OP_P     0
#define OP_RIN   4096
#define OP_ROUT  8192
#define OP_VA    12288
#define OP_VB    (12288 + VSZ)
#define OP_RED   (12288 + 2 * VSZ)
#define OP_PATCH (OP_RED + 32)
#define OP_H     (OP_PATCH + 36)
#define OP_IDX   (OP_H + 16)
#define SMEMB_FLOATS (OP_IDX + 36)

__global__ __launch_bounds__(NTB, 1)
void vin_kernel(const float* __restrict__ obs,
                const float* __restrict__ bias,
                const float* __restrict__ w1, const float* __restrict__ b1,
                const float* __restrict__ w2, const float* __restrict__ b2,
                float* __restrict__ out)
{
    extern __shared__ float sm[];
    float* sP    = sm + OP_P;
    float* sRin  = sm + OP_RIN;
    float* sRout = sm + OP_ROUT;
    float* sVa   = sm + OP_VA;
    float* sVb   = sm + OP_VB;
    float* sRed  = sm + OP_RED;
    float* sPatch= sm + OP_PATCH;
    float* sH    = sm + OP_H;
    int*   sIdx  = (int*)(sm + OP_IDX);

    const int b    = blockIdx.x;
    const int tid  = threadIdx.x;
    const int lane = tid & 31;
    const int wid  = tid >> 5;      // 0..31

    const float* pA = g_part + (size_t)(0 * BATCH + b) * NTOT;
    const float* pB = g_part + (size_t)(1 * BATCH + b) * NTOT;
    const float* pC = g_part + (size_t)(2 * BATCH + b) * NTOT;

    // ---- combine partials + bias ----
    for (int cell = tid; cell < 4096; cell += NTB) {
        int j = cell * 3;
        sRin[cell]  = pA[j]     + pB[j]     + pC[j]     + bias[j];
        sRout[cell] = pA[j + 1] + pB[j + 1] + pC[j + 1] + bias[j + 1];
        sP[cell]    = pA[j + 2] + pB[j + 2] + pC[j + 2] + bias[j + 2];
    }
    for (int i = tid; i < VSZ; i += NTB) { sVa[i] = 0.f; sVb[i] = 0.f; }
    __syncthreads();

    // ---- softmax over sP (4096) ----
    float m = -INFINITY;
    #pragma unroll
    for (int r = 0; r < 4; ++r) m = fmaxf(m, sP[tid + NTB * r]);
    #pragma unroll
    for (int off = 16; off; off >>= 1)
        m = fmaxf(m, __shfl_xor_sync(0xffffffffu, m, off));
    if (lane == 0) sRed[wid] = m;
    __syncthreads();
    float gm = sRed[0];
    #pragma unroll
    for (int i = 1; i < 32; ++i) gm = fmaxf(gm, sRed[i]);
    __syncthreads();            // protect sRed before reuse
    float s = 0.f;
    #pragma unroll
    for (int r = 0; r < 4; ++r) {
        int c = tid + NTB * r;
        float e = expf(sP[c] - gm);
        sP[c] = e; s += e;
    }
    #pragma unroll
    for (int off = 16; off; off >>= 1)
        s += __shfl_xor_sync(0xffffffffu, s, off);
    if (lane == 0) sRed[wid] = s;
    __syncthreads();
    float tot = 0.f;
    #pragma unroll
    for (int i = 0; i < 32; ++i) tot += sRed[i];
    float inv = 1.0f / tot;
    #pragma unroll
    for (int r = 0; r < 4; ++r) sP[tid + NTB * r] *= inv;
    __syncthreads();   // sP final before cross-thread pr reads

    // ---- per-cell constants straight into registers ----
    const int base = 4 * tid;
    const int h = base >> 6, w_ = base & 63;
    const int px = (h + 1) * VROW + 4 + w_;
    float pr[4], cU[4], cD[4], cL[4], cR[4], v[4];
    #pragma unroll
    for (int i = 0; i < 4; ++i) {
        const int cell = base + i;
        const float rc = sRout[cell];
        pr[i] = sP[cell];
        v[i]  = 0.f;
        float rn;
        cU[i] = (h > 0)  ? (rn = sRin[cell - 64], rn - (rn != 0.f ? rc : 0.f)) : 0.f;
        cD[i] = (h < 63) ? (rn = sRin[cell + 64], rn - (rn != 0.f ? rc : 0.f)) : 0.f;
        const int wc = w_ + i;
        cL[i] = (wc > 0)  ? (rn = sRin[cell - 1], rn - (rn != 0.f ? rc : 0.f)) : 0.f;
        cR[i] = (wc < 63) ? (rn = sRin[cell + 1], rn - (rn != 0.f ? rc : 0.f)) : 0.f;
    }

    // ---- K=64 sweeps: one run of 4 contiguous cells per thread ----
    float* cur = sVa;
    float* nxt = sVb;
    for (int itv = 0; itv < 64; ++itv) {
        const float4 up = *(const float4*)(cur + px - VROW);
        const float4 dn = *(const float4*)(cur + px + VROW);
        const float lf  = cur[px - 1];
        const float rt  = cur[px + 4];
        float n0 = fmaxf(fmaxf(fmaf(pr[0], up.x, cU[0]), fmaf(pr[0], dn.x, cD[0])),
                         fmaxf(fmaf(pr[0], lf,   cL[0]), fmaf(pr[0], v[1], cR[0])));
        float n1 = fmaxf(fmaxf(fmaf(pr[1], up.y, cU[1]), fmaf(pr[1], dn.y, cD[1])),
                         fmaxf(fmaf(pr[1], v[0], cL[1]), fmaf(pr[1], v[2], cR[1])));
        float n2 = fmaxf(fmaxf(fmaf(pr[2], up.z, cU[2]), fmaf(pr[2], dn.z, cD[2])),
                         fmaxf(fmaf(pr[2], v[1], cL[2]), fmaf(pr[2], v[3], cR[2])));
        float n3 = fmaxf(fmaxf(fmaf(pr[3], up.w, cU[3]), fmaf(pr[3], dn.w, cD[3])),
                         fmaxf(fmaf(pr[3], v[2], cL[3]), fmaf(pr[3], rt,   cR[3])));
        v[0] = fmaxf(v[0], n0);
        v[1] = fmaxf(v[1], n1);
        v[2] = fmaxf(v[2], n2);
        v[3] = fmaxf(v[3], n3);
        *(float4*)(nxt + px) = make_float4(v[0], v[1], v[2], v[3]);
        __syncthreads();
        float* t = cur; cur = nxt; nxt = t;
    }
    // final V is in `cur` (even number of swaps -> sVa)

    // ---- argmax of obs channel 1 ----
    const float* ob = obs + (size_t)b * NTOT;
    float bv = -INFINITY; int bi = 0;
    #pragma unroll
    for (int r = 0; r < 4; ++r) {
        int cell = tid + NTB * r;
        float vv = ob[cell * 3 + 1];
        if (vv > bv) { bv = vv; bi = cell; }
    }
    #pragma unroll
    for (int off = 16; off; off >>= 1) {
        float ov = __shfl_down_sync(0xffffffffu, bv, off);
        int   oi = __shfl_down_sync(0xffffffffu, bi, off);
        if (ov > bv || (ov == bv && oi < bi)) { bv = ov; bi = oi; }
    }
    if (lane == 0) { sRed[wid] = bv; sIdx[wid] = bi; }
    __syncthreads();
    if (tid == 0) {
        float bb = sRed[0]; int ii = sIdx[0];
        for (int i = 1; i < 32; ++i)
            if (sRed[i] > bb || (sRed[i] == bb && sIdx[i] < ii)) { bb = sRed[i]; ii = sIdx[i]; }
        sIdx[32] = ii;
    }
    __syncthreads();
    const int am  = sIdx[32];
    const int pi_ = am >> 6, pj_ = am & 63;

    // ---- 3x3x4 patch around agent + MLP head ----
    if (tid < 36) {
        int di = tid / 12, rem = tid % 12;
        int dj = rem >> 2, ch = rem & 3;
        float vv;
        if (ch == 3) {
            vv = cur[(pi_ + di) * VROW + 3 + pj_ + dj];   // V(pi_+di-1, pj_+dj-1)
        } else {
            int hh = pi_ + di - 1, ww = pj_ + dj - 1;
            vv = (hh >= 0 && hh < 64 && ww >= 0 && ww < 64)
                    ? ob[(hh * 64 + ww) * 3 + ch] : 0.f;
        }
        sPatch[tid] = vv;
    }
    __syncthreads();
    if (tid < 16) {
        float a = b1[tid];
        #pragma unroll
        for (int i = 0; i < 36; ++i) a = fmaf(sPatch[i], w1[i * 16 + tid], a);
        sH[tid] = fmaxf(a, 0.f);
    }
    __syncthreads();
    if (tid < 4) {
        float a = b2[tid];
        #pragma unroll
        for (int o = 0; o < 16; ++o) a = fmaf(sH[o], w2[o * 4 + tid], a);
        out[b * 4 + tid] = a;
    }
}

// ================= launcher =================
extern "C" void kernel_launch(void* const* d_in, const int* in_sizes, int n_in,
                              void* d_out, int out_size)
{
    const float* obs  = (const float*)d_in[0];
    const float* phiw = (const float*)d_in[1];
    const float* phib = (const float*)d_in[2];
    const float* w1   = (const float*)d_in[3];
    const float* b1   = (const float*)d_in[4];
    const float* w2   = (const float*)d_in[5];
    const float* b2   = (const float*)d_in[6];
    float* out = (float*)d_out;

    const int smemA = SMEMA_TOTAL;                        // 27648 B
    const int smemB = SMEMB_FLOATS * (int)sizeof(float);  // ~85.6 KB

    cudaFuncSetAttribute(gemm_mma,   cudaFuncAttributeMaxDynamicSharedMemorySize, smemA);
    cudaFuncSetAttribute(vin_kernel, cudaFuncAttributeMaxDynamicSharedMemorySize, smemB);

    gemm_mma<<<dim3(NTOT / NTILE, NKC), 256, smemA>>>(obs, phiw);
    vin_kernel<<<BATCH, NTB, smemB>>>(obs, phib, w1, b1, w2, b2, out);
}

// round 15
// speedup vs baseline: 1.1622x; 1.1622x over previous
#include <cuda_runtime.h>
#include <math.h>

// ---------------- problem constants ----------------
#define NTOT   12288         // H*W*3
#define BATCH  64
#define KCH    4096          // K per k-split slice
#define NKC    3
#define NTILE  128           // output cols per CTA
#define KSTAGE 32            // k per smem stage
#define NSTAGE (KCH / KSTAGE)   // 128

// k-split partials: [NKC][BATCH][NTOT]  (~9.4 MB scratch)
__device__ __align__(16) float g_part[NKC * BATCH * NTOT];

// ---------------- smem layout (bytes) ----------------
// AH planes : [2 buf][64 m][80 B]   (32 fp16 + pad)  -> 10240
// BH planes : [2 buf][32 k][272 B]  (128 fp16 + pad) -> 17408
// B fp32 ring: [3 slots][16384 B]   (raw cp.async)   -> 49152
#define A_STRIDE 80
#define B_STRIDE 272
#define OFF_AH   0
#define OFF_BH   10240
#define OFF_RING 27648
#define RING_STAGE 16384
#define SMEMA_TOTAL 76800

__device__ __forceinline__ unsigned smem_u32(const void* p) {
    unsigned a;
    asm("{ .reg .u64 t; cvta.to.shared.u64 t, %1; cvt.u32.u64 %0, t; }" : "=r"(a) : "l"(p));
    return a;
}

// pack two f32 -> f16x2 (lo = a, hi = b)
__device__ __forceinline__ unsigned packf16(float a, float b) {
    unsigned r;
    asm("cvt.rn.f16x2.f32 %0, %1, %2;" : "=r"(r) : "f"(b), "f"(a));
    return r;
}

#define CP_ASYNC16(dst, src) \
    asm volatile("cp.async.cg.shared.global [%0], [%1], 16;" :: "r"(dst), "l"(src))
#define CP_COMMIT() \
    asm volatile("cp.async.commit_group;" ::: "memory")
#define CP_WAIT2() \
    asm volatile("cp.async.wait_group 2;" ::: "memory")

#define LDMX4(r0, r1, r2, r3, addr) \
    asm volatile("ldmatrix.sync.aligned.m8n8.x4.shared.b16 {%0,%1,%2,%3}, [%4];" \
                 : "=r"(r0), "=r"(r1), "=r"(r2), "=r"(r3) : "r"(addr))
#define LDMX4T(r0, r1, r2, r3, addr) \
    asm volatile("ldmatrix.sync.aligned.m8n8.x4.trans.shared.b16 {%0,%1,%2,%3}, [%4];" \
                 : "=r"(r0), "=r"(r1), "=r"(r2), "=r"(r3) : "r"(addr))
#define MMA16816(d, a, b) \
    asm volatile("mma.sync.aligned.m16n8k16.row.col.f32.f16.f16.f32 " \
                 "{%0,%1,%2,%3}, {%4,%5,%6,%7}, {%8,%9}, {%0,%1,%2,%3};" \
                 : "+f"((d)[0]), "+f"((d)[1]), "+f"((d)[2]), "+f"((d)[3]) \
                 : "r"((a)[0]), "r"((a)[1]), "r"((a)[2]), "r"((a)[3]), \
                   "r"((b)[0]), "r"((b)[1]))

// ================= Kernel A: mma.sync fp16 GEMM, cp.async W stream =================
// C[64, 128] partial over k-chunk 4096. 8 warps = 2M x 4N, warp 32x32.
// W staged fp32 through a 3-deep cp.async smem ring (no register WAR),
// converted fp16 per stage (thread-local ring chunks -> no extra barrier).
__global__ __launch_bounds__(256, 2)
void gemm_mma(const float* __restrict__ obs, const float* __restrict__ W)
{
    extern __shared__ char smem[];
    const unsigned sbase = smem_u32(smem);
    const int tid  = threadIdx.x;
    const int lane = tid & 31;
    const int wid  = tid >> 5;
    const int n0   = blockIdx.x * NTILE;
    const int k0   = blockIdx.y * KCH;

    const int wm = wid >> 2;
    const int wn = wid & 3;
    const int mbase = 32 * wm;
    const int nbase = 32 * wn;

    // loader mappings
    const int am = tid >> 2;          // A row m 0..63
    const int aq = tid & 3;           // A k-octet

    // ldmatrix lane address components
    const int a_mo = ((lane >> 3) & 1) * 8 + (lane & 7);
    const int a_ko = (lane >> 4) * 8;
    const int b_k  = lane & 15;
    const int b_no = (lane >> 4) * 8;

    float4 a4[2];

    // prologue: A(0) regs; cp.async B stages 0..2 into ring slots 0..2
    {
        const float* ap = obs + (size_t)am * NTOT + k0 + 8 * aq;
        a4[0] = *(const float4*)ap;
        a4[1] = *(const float4*)(ap + 4);
    }
    #pragma unroll
    for (int st = 0; st < 3; ++st) {
        #pragma unroll
        for (int p = 0; p < 4; ++p) {
            const unsigned dst = sbase + OFF_RING + st * RING_STAGE + (p * 256 + tid) * 16;
            const float* src = W + (size_t)(k0 + st * KSTAGE + wid + 8 * p) * NTOT + n0 + 4 * lane;
            CP_ASYNC16(dst, src);
        }
        CP_COMMIT();
    }

    float acc[2][4][4];
    #pragma unroll
    for (int mf = 0; mf < 2; ++mf)
        #pragma unroll
        for (int nf = 0; nf < 4; ++nf)
            #pragma unroll
            for (int q = 0; q < 4; ++q) acc[mf][nf][q] = 0.f;

    int slot3 = 0;   // ring slot for current stage s (s % 3)

    for (int s = 0; s < NSTAGE; ++s) {
        const int buf = s & 1;

        CP_WAIT2();   // group for stage s complete (invariant: 3 groups pending)

        // ---- B: ring(fp32) -> cvt -> BH(fp16), thread-local chunks ----
        {
            char* BH = smem + OFF_BH + buf * 8704;
            const char* RP = smem + OFF_RING + slot3 * RING_STAGE;
            #pragma unroll
            for (int p = 0; p < 4; ++p) {
                const float4 f = *(const float4*)(RP + (p * 256 + tid) * 16);
                const unsigned h0 = packf16(f.x, f.y);
                const unsigned h1 = packf16(f.z, f.w);
                const unsigned boff = (unsigned)((wid + 8 * p) * B_STRIDE + 8 * lane);
                *(uint2*)(BH + boff) = make_uint2(h0, h1);
            }
        }
        // ---- A: cvt + STS stage s ----
        {
            char* AH = smem + OFF_AH + buf * 5120;
            unsigned h0 = packf16(a4[0].x, a4[0].y);
            unsigned h1 = packf16(a4[0].z, a4[0].w);
            unsigned h2 = packf16(a4[1].x, a4[1].y);
            unsigned h3 = packf16(a4[1].z, a4[1].w);
            *(uint4*)(AH + (unsigned)(am * A_STRIDE + 16 * aq)) = make_uint4(h0, h1, h2, h3);
        }
        // ---- A: LDG stage s+1 (L2-resident; distance-1 suffices) ----
        if (s + 1 < NSTAGE) {
            const float* ap = obs + (size_t)am * NTOT + k0 + (s + 1) * KSTAGE + 8 * aq;
            a4[0] = *(const float4*)ap;
            a4[1] = *(const float4*)(ap + 4);
        }
        // ---- B: cp.async stage s+3 into this slot (reads above are done) ----
        if (s + 3 < NSTAGE) {
            #pragma unroll
            for (int p = 0; p < 4; ++p) {
                const unsigned dst = sbase + OFF_RING + slot3 * RING_STAGE + (p * 256 + tid) * 16;
                const float* src = W + (size_t)(k0 + (s + 3) * KSTAGE + wid + 8 * p) * NTOT + n0 + 4 * lane;
                CP_ASYNC16(dst, src);
            }
        }
        CP_COMMIT();   // unconditional (empty groups keep wait invariant exact)
        slot3 = (slot3 + 1 == 3) ? 0 : slot3 + 1;

        __syncthreads();   // single barrier per stage (ping-pong WAR-safe)

        // ---- compute stage s: 2 k16 steps, single pass ----
        const unsigned AHb = sbase + OFF_AH + buf * 5120;
        const unsigned BHb = sbase + OFF_BH + buf * 8704;

        #pragma unroll
        for (int kb = 0; kb < 2; ++kb) {
            unsigned ah[2][4];
            #pragma unroll
            for (int mf = 0; mf < 2; ++mf) {
                const unsigned aoff =
                    (unsigned)((mbase + 16 * mf + a_mo) * A_STRIDE + (kb * 16 + a_ko) * 2);
                LDMX4(ah[mf][0], ah[mf][1], ah[mf][2], ah[mf][3], AHb + aoff);
            }
            unsigned bh[4][2];
            #pragma unroll
            for (int g = 0; g < 2; ++g) {
                const unsigned boff =
                    (unsigned)((kb * 16 + b_k) * B_STRIDE + (nbase + 16 * g + b_no) * 2);
                LDMX4T(bh[2*g][0], bh[2*g][1], bh[2*g+1][0], bh[2*g+1][1], BHb + boff);
            }
            #pragma unroll
            for (int mf = 0; mf < 2; ++mf)
                #pragma unroll
                for (int nf = 0; nf < 4; ++nf)
                    MMA16816(acc[mf][nf], ah[mf], bh[nf]);
        }
    }

    // ---- epilogue ----
    float* op = g_part + (size_t)blockIdx.y * (BATCH * NTOT);
    const int r0 = lane >> 2;
    const int c0 = 2 * (lane & 3);
    #pragma unroll
    for (int mf = 0; mf < 2; ++mf)
        #pragma unroll
        for (int nf = 0; nf < 4; ++nf) {
            const int m = mbase + 16 * mf + r0;
            const int n = n0 + nbase + 8 * nf + c0;
            *(float2*)(op + (size_t)m * NTOT + n) =
                make_float2(acc[mf][nf][0], acc[mf][nf][1]);
            *(float2*)(op + (size_t)(m + 8) * NTOT + n) =
                make_float2(acc[mf][nf][2], acc[mf][nf][3]);
        }
}

// ================= Kernel B: combine + softmax + VIN + head =================
// 1024 threads, no sC staging (constants straight to registers).
// V padded grid: 66 rows x stride 68, left-pad 4: V(h,w) at (h+1)*68 + 4 + w.
#define NTB  1024
#define VROW 68
#define VSZ  (66 * VROW)     // 4488
#define OP_P     0
#define OP_RIN   4096
#define OP_ROUT  8192
#define OP_VA    12288
#define OP_VB    (12288 + VSZ)
#define OP_RED   (12288 + 2 * VSZ)
#define OP_PATCH (OP_RED + 32)
#define OP_H     (OP_PATCH + 36)
#define OP_IDX   (OP_H + 16)
#define SMEMB_FLOATS (OP_IDX + 36)

__global__ __launch_bounds__(NTB, 1)
void vin_kernel(const float* __restrict__ obs,
                const float* __restrict__ bias,
                const float* __restrict__ w1, const float* __restrict__ b1,
                const float* __restrict__ w2, const float* __restrict__ b2,
                float* __restrict__ out)
{
    extern __shared__ float sm[];
    float* sP    = sm + OP_P;
    float* sRin  = sm + OP_RIN;
    float* sRout = sm + OP_ROUT;
    float* sVa   = sm + OP_VA;
    float* sVb   = sm + OP_VB;
    float* sRed  = sm + OP_RED;
    float* sPatch= sm + OP_PATCH;
    float* sH    = sm + OP_H;
    int*   sIdx  = (int*)(sm + OP_IDX);

    const int b    = blockIdx.x;
    const int tid  = threadIdx.x;
    const int lane = tid & 31;
    const int wid  = tid >> 5;      // 0..31

    const float* pA = g_part + (size_t)(0 * BATCH + b) * NTOT;
    const float* pB = g_part + (size_t)(1 * BATCH + b) * NTOT;
    const float* pC = g_part + (size_t)(2 * BATCH + b) * NTOT;

    // ---- combine partials + bias ----
    for (int cell = tid; cell < 4096; cell += NTB) {
        int j = cell * 3;
        sRin[cell]  = pA[j]     + pB[j]     + pC[j]     + bias[j];
        sRout[cell] = pA[j + 1] + pB[j + 1] + pC[j + 1] + bias[j + 1];
        sP[cell]    = pA[j + 2] + pB[j + 2] + pC[j + 2] + bias[j + 2];
    }
    for (int i = tid; i < VSZ; i += NTB) { sVa[i] = 0.f; sVb[i] = 0.f; }
    __syncthreads();

    // ---- softmax over sP (4096) ----
    float m = -INFINITY;
    #pragma unroll
    for (int r = 0; r < 4; ++r) m = fmaxf(m, sP[tid + NTB * r]);
    #pragma unroll
    for (int off = 16; off; off >>= 1)
        m = fmaxf(m, __shfl_xor_sync(0xffffffffu, m, off));
    if (lane == 0) sRed[wid] = m;
    __syncthreads();
    float gm = sRed[0];
    #pragma unroll
    for (int i = 1; i < 32; ++i) gm = fmaxf(gm, sRed[i]);
    __syncthreads();            // protect sRed before reuse
    float s = 0.f;
    #pragma unroll
    for (int r = 0; r < 4; ++r) {
        int c = tid + NTB * r;
        float e = expf(sP[c] - gm);
        sP[c] = e; s += e;
    }
    #pragma unroll
    for (int off = 16; off; off >>= 1)
        s += __shfl_xor_sync(0xffffffffu, s, off);
    if (lane == 0) sRed[wid] = s;
    __syncthreads();
    float tot = 0.f;
    #pragma unroll
    for (int i = 0; i < 32; ++i) tot += sRed[i];
    float inv = 1.0f / tot;
    #pragma unroll
    for (int r = 0; r < 4; ++r) sP[tid + NTB * r] *= inv;
    __syncthreads();   // sP final before cross-thread pr reads

    // ---- per-cell constants straight into registers ----
    const int base = 4 * tid;
    const int h = base >> 6, w_ = base & 63;
    const int px = (h + 1) * VROW + 4 + w_;
    float pr[4], cU[4], cD[4], cL[4], cR[4], v[4];
    #pragma unroll
    for (int i = 0; i < 4; ++i) {
        const int cell = base + i;
        const float rc = sRout[cell];
        pr[i] = sP[cell];
        v[i]  = 0.f;
        float rn;
        cU[i] = (h > 0)  ? (rn = sRin[cell - 64], rn - (rn != 0.f ? rc : 0.f)) : 0.f;
        cD[i] = (h < 63) ? (rn = sRin[cell + 64], rn - (rn != 0.f ? rc : 0.f)) : 0.f;
        const int wc = w_ + i;
        cL[i] = (wc > 0)  ? (rn = sRin[cell - 1], rn - (rn != 0.f ? rc : 0.f)) : 0.f;
        cR[i] = (wc < 63) ? (rn = sRin[cell + 1], rn - (rn != 0.f ? rc : 0.f)) : 0.f;
    }

    // ---- K=64 sweeps: one run of 4 contiguous cells per thread ----
    float* cur = sVa;
    float* nxt = sVb;
    for (int itv = 0; itv < 64; ++itv) {
        const float4 up = *(const float4*)(cur + px - VROW);
        const float4 dn = *(const float4*)(cur + px + VROW);
        const float lf  = cur[px - 1];
        const float rt  = cur[px + 4];
        float n0 = fmaxf(fmaxf(fmaf(pr[0], up.x, cU[0]), fmaf(pr[0], dn.x, cD[0])),
                         fmaxf(fmaf(pr[0], lf,   cL[0]), fmaf(pr[0], v[1], cR[0])));
        float n1 = fmaxf(fmaxf(fmaf(pr[1], up.y, cU[1]), fmaf(pr[1], dn.y, cD[1])),
                         fmaxf(fmaf(pr[1], v[0], cL[1]), fmaf(pr[1], v[2], cR[1])));
        float n2 = fmaxf(fmaxf(fmaf(pr[2], up.z, cU[2]), fmaf(pr[2], dn.z, cD[2])),
                         fmaxf(fmaf(pr[2], v[1], cL[2]), fmaf(pr[2], v[3], cR[2])));
        float n3 = fmaxf(fmaxf(fmaf(pr[3], up.w, cU[3]), fmaf(pr[3], dn.w, cD[3])),
                         fmaxf(fmaf(pr[3], v[2], cL[3]), fmaf(pr[3], rt,   cR[3])));
        v[0] = fmaxf(v[0], n0);
        v[1] = fmaxf(v[1], n1);
        v[2] = fmaxf(v[2], n2);
        v[3] = fmaxf(v[3], n3);
        *(float4*)(nxt + px) = make_float4(v[0], v[1], v[2], v[3]);
        __syncthreads();
        float* t = cur; cur = nxt; nxt = t;
    }
    // final V is in `cur` (even number of swaps -> sVa)

    // ---- argmax of obs channel 1 ----
    const float* ob = obs + (size_t)b * NTOT;
    float bv = -INFINITY; int bi = 0;
    #pragma unroll
    for (int r = 0; r < 4; ++r) {
        int cell = tid + NTB * r;
        float vv = ob[cell * 3 + 1];
        if (vv > bv) { bv = vv; bi = cell; }
    }
    #pragma unroll
    for (int off = 16; off; off >>= 1) {
        float ov = __shfl_down_sync(0xffffffffu, bv, off);
        int   oi = __shfl_down_sync(0xffffffffu, bi, off);
        if (ov > bv || (ov == bv && oi < bi)) { bv = ov; bi = oi; }
    }
    if (lane == 0) { sRed[wid] = bv; sIdx[wid] = bi; }
    __syncthreads();
    if (tid == 0) {
        float bb = sRed[0]; int ii = sIdx[0];
        for (int i = 1; i < 32; ++i)
            if (sRed[i] > bb || (sRed[i] == bb && sIdx[i] < ii)) { bb = sRed[i]; ii = sIdx[i]; }
        sIdx[32] = ii;
    }
    __syncthreads();
    const int am  = sIdx[32];
    const int pi_ = am >> 6, pj_ = am & 63;

    // ---- 3x3x4 patch around agent + MLP head ----
    if (tid < 36) {
        int di = tid / 12, rem = tid % 12;
        int dj = rem >> 2, ch = rem & 3;
        float vv;
        if (ch == 3) {
            vv = cur[(pi_ + di) * VROW + 3 + pj_ + dj];   // V(pi_+di-1, pj_+dj-1)
        } else {
            int hh = pi_ + di - 1, ww = pj_ + dj - 1;
            vv = (hh >= 0 && hh < 64 && ww >= 0 && ww < 64)
                    ? ob[(hh * 64 + ww) * 3 + ch] : 0.f;
        }
        sPatch[tid] = vv;
    }
    __syncthreads();
    if (tid < 16) {
        float a = b1[tid];
        #pragma unroll
        for (int i = 0; i < 36; ++i) a = fmaf(sPatch[i], w1[i * 16 + tid], a);
        sH[tid] = fmaxf(a, 0.f);
    }
    __syncthreads();
    if (tid < 4) {
        float a = b2[tid];
        #pragma unroll
        for (int o = 0; o < 16; ++o) a = fmaf(sH[o], w2[o * 4 + tid], a);
        out[b * 4 + tid] = a;
    }
}

// ================= launcher =================
extern "C" void kernel_launch(void* const* d_in, const int* in_sizes, int n_in,
                              void* d_out, int out_size)
{
    const float* obs  = (const float*)d_in[0];
    const float* phiw = (const float*)d_in[1];
    const float* phib = (const float*)d_in[2];
    const float* w1   = (const float*)d_in[3];
    const float* b1   = (const float*)d_in[4];
    const float* w2   = (const float*)d_in[5];
    const float* b2   = (const float*)d_in[6];
    float* out = (float*)d_out;

    const int smemA = SMEMA_TOTAL;                        // 76800 B
    const int smemB = SMEMB_FLOATS * (int)sizeof(float);  // ~85.6 KB

    cudaFuncSetAttribute(gemm_mma,   cudaFuncAttributeMaxDynamicSharedMemorySize, smemA);
    cudaFuncSetAttribute(vin_kernel, cudaFuncAttributeMaxDynamicSharedMemorySize, smemB);

    gemm_mma<<<dim3(NTOT / NTILE, NKC), 256, smemA>>>(obs, phiw);
    vin_kernel<<<BATCH, NTB, smemB>>>(obs, phib, w1, b1, w2, b2, out);
}